// round 16
// baseline (speedup 1.0000x reference)
#include <cuda_runtime.h>
#include <math.h>
#include <stdint.h>

#define BB   2
#define NN   768
#define TT   96
#define FMF  8
#define HIDD 64
#define TDD  32

#define NTILE 24           // 768/32
#define NUPPER 300         // 24*25/2
#define TOTTILES (NUPPER * BB)
#define GRIDP 592          // 148 SMs * 2 CTAs
#define GRIDN 96           // 1536 / 16 nodes per block
#define PAD 68             // h tiles: word-pad for conflict-light LDS.64
#define SPQ 144            // PQ tiles: stride 144 -> LDS.128 phase-conflict-free

// ---------------------------------------------------------------------------
// helpers
// ---------------------------------------------------------------------------
__device__ __forceinline__ uint32_t pack_bf16(float lo, float hi) {
    uint32_t r;
    asm("cvt.rn.bf16x2.f32 %0, %1, %2;" : "=r"(r) : "f"(hi), "f"(lo));
    return r;
}

// tanh(x) = 1 - 2/(e^{2x}+1), via ex2.approx + rcp.approx.
__device__ __forceinline__ float fast_tanh(float x) {
    float e;
    asm("ex2.approx.f32 %0, %1;" : "=f"(e) : "f"(x * 2.8853900818f)); // 2x*log2(e)
    float r;
    asm("rcp.approx.f32 %0, %1;" : "=f"(r) : "f"(e + 1.0f));
    return fmaf(-2.0f, r, 1.0f);
}

__device__ __forceinline__ void mma_bf16(float* d,
                                         uint32_t a0, uint32_t a1, uint32_t a2, uint32_t a3,
                                         uint32_t b0, uint32_t b1) {
    asm volatile(
        "mma.sync.aligned.m16n8k16.row.col.f32.bf16.bf16.f32 "
        "{%0,%1,%2,%3}, {%4,%5,%6,%7}, {%8,%9}, {%0,%1,%2,%3};"
        : "+f"(d[0]), "+f"(d[1]), "+f"(d[2]), "+f"(d[3])
        : "r"(a0), "r"(a1), "r"(a2), "r"(a3), "r"(b0), "r"(b1));
}

// Scratch (allocation-free rule: __device__ globals)
__device__ float g_h[BB * NN * HIDD];
__device__ float g_P[BB * NN * HIDD];     // h @ w_i + ps_b1
__device__ float g_Q[BB * NN * HIDD];     // h @ w_j
__device__ float g_stats[BB * NN * 12];   // [0]=last [1]=mean [2]=max [4..11]=mark means

// ---------------------------------------------------------------------------
// Kernel 0: stats — one 128-thread block per node; pure-bandwidth input phase
// at high occupancy. Block 0 also writes lam to the output tail.
// ---------------------------------------------------------------------------
__global__ __launch_bounds__(128)
void stats_kernel(const float* __restrict__ x_hist, const float* __restrict__ x_mark,
                  const float* __restrict__ raw_lambda,
                  float* __restrict__ out, int out_size)
{
    const int node = blockIdx.x;
    const int tid  = threadIdx.x;

    __shared__ float red[128][8];
    __shared__ float hsum[128], hmax[128], hlast;

    // x_mark: 768 floats = 192 float4; float4 p even -> features 0-3, odd -> 4-7
    const float4* xm4 = (const float4*)(x_mark + (size_t)node * TT * FMF);
    float a[8];
    #pragma unroll
    for (int k = 0; k < 8; k++) a[k] = 0.f;
    {
        float4 v = xm4[tid];
        int off = (tid & 1) * 4;
        a[off + 0] += v.x; a[off + 1] += v.y; a[off + 2] += v.z; a[off + 3] += v.w;
        if (tid < 64) {
            float4 v2 = xm4[tid + 128];
            a[off + 0] += v2.x; a[off + 1] += v2.y; a[off + 2] += v2.z; a[off + 3] += v2.w;
        }
    }

    // x_hist: 96 floats
    const float* xh = x_hist + (size_t)node * TT;
    float hv = (tid < TT) ? xh[tid] : 0.f;
    hsum[tid] = hv;
    hmax[tid] = (tid < TT) ? hv : -3.0e38f;
    if (tid == TT - 1) hlast = hv;
    #pragma unroll
    for (int k = 0; k < 8; k++) red[tid][k] = a[k];
    __syncthreads();

    #pragma unroll
    for (int off = 64; off > 0; off >>= 1) {
        if (tid < off) {
            #pragma unroll
            for (int k = 0; k < 8; k++) red[tid][k] += red[tid + off][k];
            hsum[tid] += hsum[tid + off];
            hmax[tid] = fmaxf(hmax[tid], hmax[tid + off]);
        }
        __syncthreads();
    }

    float* gs = g_stats + (size_t)node * 12;
    if (tid == 0) {
        gs[0] = hlast;
        gs[1] = hsum[0] * (1.f / (float)TT);
        gs[2] = hmax[0];
        if (node == 0) {
            const float lam = 1.f / (1.f + expf(-raw_lambda[0]));
            for (int idx = BB * NN * NN; idx < out_size; idx++) out[idx] = lam;
        }
    }
    if (tid < 8) gs[4 + tid] = red[0][tid] * (1.f / (float)TT);
}

// ---------------------------------------------------------------------------
// Kernel 1: per-node MLP chain, GEMM-style. 96 blocks x 16 nodes.
// ---------------------------------------------------------------------------
#define O_TE1 0                      // 96
#define O_TB1 (O_TE1 + 96)           // 32
#define O_ME1 (O_TB1 + 32)           // 256
#define O_MB1 (O_ME1 + 256)          // 32
#define O_TE2 (O_MB1 + 32)           // 1024
#define O_TB2 (O_TE2 + 1024)         // 32
#define O_ME2 (O_TB2 + 32)           // 1024
#define O_MB2 (O_ME2 + 1024)         // 32
#define O_NFW (O_MB2 + 32)           // 4096
#define O_NFB (O_NFW + 4096)         // 64
#define O_WI  (O_NFB + 64)           // 4096
#define O_WJ  (O_WI + 4096)          // 4096
#define O_PB1 (O_WJ + 4096)          // 64
#define O_ST  (O_PB1 + 64)           // 16*4
#define O_MS  (O_ST + 64)            // 16*8
#define O_L1  (O_MS + 128)           // 16*64
#define O_L2  (O_L1 + 1024)          // 16*64
#define O_H   (O_L2 + 1024)          // 16*64
#define NODE_SM_FLOATS (O_H + 1024)
#define NODE_SM_BYTES (NODE_SM_FLOATS * 4)

__global__ __launch_bounds__(256)
void node_kernel(const float* __restrict__ te_w1, const float* __restrict__ te_b1,
                 const float* __restrict__ te_w2, const float* __restrict__ te_b2,
                 const float* __restrict__ me_w1, const float* __restrict__ me_b1,
                 const float* __restrict__ me_w2, const float* __restrict__ me_b2,
                 const float* __restrict__ nf_w,  const float* __restrict__ nf_b,
                 const float* __restrict__ ps_w1, const float* __restrict__ ps_b1)
{
    extern __shared__ float sw[];
    const int tid = threadIdx.x;

    // ---- stage weights (float4) ----
    {
        float4*       dNF = (float4*)(sw + O_NFW);
        float4*       dWI = (float4*)(sw + O_WI);
        float4*       dWJ = (float4*)(sw + O_WJ);
        const float4* sNF = (const float4*)nf_w;
        const float4* sWI = (const float4*)ps_w1;
        const float4* sWJ = (const float4*)(ps_w1 + HIDD * HIDD);
        #pragma unroll
        for (int e = tid; e < 1024; e += 256) {
            dNF[e] = sNF[e]; dWI[e] = sWI[e]; dWJ[e] = sWJ[e];
        }
        ((float4*)(sw + O_TE2))[tid] = ((const float4*)te_w2)[tid];
        ((float4*)(sw + O_ME2))[tid] = ((const float4*)me_w2)[tid];
        if (tid < 96) sw[O_TE1 + tid] = te_w1[tid];
        if (tid < 64) ((float4*)(sw + O_ME1))[tid] = ((const float4*)me_w1)[tid];
        if (tid < 32) {
            sw[O_TB1 + tid] = te_b1[tid]; sw[O_MB1 + tid] = me_b1[tid];
            sw[O_TB2 + tid] = te_b2[tid]; sw[O_MB2 + tid] = me_b2[tid];
        }
        if (tid < 16) {
            ((float4*)(sw + O_NFB))[tid] = ((const float4*)nf_b)[tid];
            ((float4*)(sw + O_PB1))[tid] = ((const float4*)ps_b1)[tid];
        }
        // stats for this block's 16 nodes
        for (int e = tid; e < 16 * 12; e += 256) {
            int n = e / 12, f = e - n * 12;
            float v = g_stats[(size_t)(blockIdx.x * 16 + n) * 12 + f];
            if (f < 4) sw[O_ST + n * 4 + f] = v;
            else       sw[O_MS + n * 8 + (f - 4)] = v;
        }
    }
    __syncthreads();

    const int n   = tid >> 4;          // node in block (0..15)
    const int s   = tid & 15;
    const int ch0 = 2 * s;
    const int ch4 = 4 * s;
    const int node = blockIdx.x * 16 + n;

    // ---- layer 1 ----
    {
        float2 t1 = *(const float2*)&sw[O_TB1 + ch0];
        #pragma unroll
        for (int c = 0; c < 3; c++) {
            float sv = sw[O_ST + n * 4 + c];
            float2 wv = *(const float2*)&sw[O_TE1 + c * TDD + ch0];
            t1.x = fmaf(sv, wv.x, t1.x); t1.y = fmaf(sv, wv.y, t1.y);
        }
        float2 m1 = *(const float2*)&sw[O_MB1 + ch0];
        #pragma unroll
        for (int c = 0; c < FMF; c++) {
            float sv = sw[O_MS + n * 8 + c];
            float2 wv = *(const float2*)&sw[O_ME1 + c * TDD + ch0];
            m1.x = fmaf(sv, wv.x, m1.x); m1.y = fmaf(sv, wv.y, m1.y);
        }
        *(float2*)&sw[O_L1 + n * 64 + ch0]      = make_float2(fmaxf(t1.x, 0.f), fmaxf(t1.y, 0.f));
        *(float2*)&sw[O_L1 + n * 64 + 32 + ch0] = make_float2(fmaxf(m1.x, 0.f), fmaxf(m1.y, 0.f));
    }
    __syncthreads();

    // ---- layer 2 ----
    {
        float2 t2 = *(const float2*)&sw[O_TB2 + ch0];
        float2 m2 = *(const float2*)&sw[O_MB2 + ch0];
        #pragma unroll
        for (int c = 0; c < TDD; c++) {
            float tv = sw[O_L1 + n * 64 + c];
            float mv = sw[O_L1 + n * 64 + 32 + c];
            float2 wt = *(const float2*)&sw[O_TE2 + c * TDD + ch0];
            float2 wm = *(const float2*)&sw[O_ME2 + c * TDD + ch0];
            t2.x = fmaf(tv, wt.x, t2.x); t2.y = fmaf(tv, wt.y, t2.y);
            m2.x = fmaf(mv, wm.x, m2.x); m2.y = fmaf(mv, wm.y, m2.y);
        }
        *(float2*)&sw[O_L2 + n * 64 + ch0]      = t2;
        *(float2*)&sw[O_L2 + n * 64 + 32 + ch0] = m2;
    }
    __syncthreads();

    // ---- node fuse ----
    {
        float4 h = *(const float4*)&sw[O_NFB + ch4];
        #pragma unroll 8
        for (int c = 0; c < HIDD; c++) {
            float a = sw[O_L2 + n * 64 + c];
            float4 wv = *(const float4*)&sw[O_NFW + c * HIDD + ch4];
            h.x = fmaf(a, wv.x, h.x); h.y = fmaf(a, wv.y, h.y);
            h.z = fmaf(a, wv.z, h.z); h.w = fmaf(a, wv.w, h.w);
        }
        h.x = fmaxf(h.x, 0.f); h.y = fmaxf(h.y, 0.f);
        h.z = fmaxf(h.z, 0.f); h.w = fmaxf(h.w, 0.f);
        *(float4*)&sw[O_H + n * 64 + ch4] = h;
        *(float4*)&g_h[(size_t)node * HIDD + ch4] = h;
    }
    __syncthreads();

    // ---- P / Q ----
    {
        float4 P = *(const float4*)&sw[O_PB1 + ch4];
        float4 Q = make_float4(0.f, 0.f, 0.f, 0.f);
        #pragma unroll 8
        for (int c = 0; c < HIDD; c++) {
            float hv = sw[O_H + n * 64 + c];
            float4 wi = *(const float4*)&sw[O_WI + c * HIDD + ch4];
            float4 wj = *(const float4*)&sw[O_WJ + c * HIDD + ch4];
            P.x = fmaf(hv, wi.x, P.x); P.y = fmaf(hv, wi.y, P.y);
            P.z = fmaf(hv, wi.z, P.z); P.w = fmaf(hv, wi.w, P.w);
            Q.x = fmaf(hv, wj.x, Q.x); Q.y = fmaf(hv, wj.y, Q.y);
            Q.z = fmaf(hv, wj.z, Q.z); Q.w = fmaf(hv, wj.w, Q.w);
        }
        *(float4*)&g_P[(size_t)node * HIDD + ch4] = P;
        *(float4*)&g_Q[(size_t)node * HIDD + ch4] = Q;
    }
}

// ---------------------------------------------------------------------------
// Kernel 2: pairwise delta via bf16 m16n8k16. Two i-rows per warp, persistent
// A-fragments, quarter-N acc, float4-interleaved P/Q.
// ---------------------------------------------------------------------------
#define BF_BYTES (4 * 4 * 32 * 16)                   // uint4 table, 8 KB
#define SM_FLOATS_P (2 * 32 * PAD + 2 * 32 * SPQ + 64)
#define SM_BYTES (BF_BYTES + SM_FLOATS_P * 4)

__global__ __launch_bounds__(256, 2)
void pair_kernel(const float* __restrict__ ps_w1, const float* __restrict__ ps_w2,
                 const float* __restrict__ ps_b2, float* __restrict__ out)
{
    extern __shared__ __align__(16) char smx[];
    uint4* Bq = (uint4*)smx;                         // [kt][q][lane]
    float* fp = (float*)(smx + BF_BYTES);
    float* hI  = fp;                                 // [32][PAD]
    float* hJ  = hI + 32 * PAD;
    float* PQI = hJ + 32 * PAD;                      // [32][SPQ]
    float* PQJ = PQI + 32 * SPQ;
    float* w2s = PQJ + 32 * SPQ;                     // [64]

    const int tid  = threadIdx.x;
    const int w    = tid >> 5;
    const int lane = tid & 31;
    const int gid  = lane >> 2;                      // 0..7
    const int tig  = lane & 3;                       // 0..3

    // B fragment table (uint4 of bf16x2), tile-independent: load once.
    {
        const float* wd = ps_w1 + 128 * HIDD;
        for (int e = tid; e < 4 * 4 * 32; e += 256) {
            int ktp = e >> 5, ln = e & 31;
            int kt = ktp >> 2, q = ktp & 3;
            int gd = ln >> 2, tg = ln & 3;
            int k0 = kt * 16 + 2 * tg;
            int n0 = 2 * q * 8 + gd, n1 = n0 + 8;
            uint4 v;
            v.x = pack_bf16(wd[k0 * HIDD + n0],       wd[(k0 + 1) * HIDD + n0]);
            v.y = pack_bf16(wd[(k0 + 8) * HIDD + n0], wd[(k0 + 9) * HIDD + n0]);
            v.z = pack_bf16(wd[k0 * HIDD + n1],       wd[(k0 + 1) * HIDD + n1]);
            v.w = pack_bf16(wd[(k0 + 8) * HIDD + n1], wd[(k0 + 9) * HIDD + n1]);
            Bq[(size_t)ktp * 32 + ln] = v;
        }
    }
    if (tid < 64) w2s[tid] = ps_w2[tid];
    const float b2v = ps_b2[0];

    #pragma unroll 1
    for (int t = blockIdx.x; t < TOTTILES; t += GRIDP) {
        const int b = t / NUPPER;
        int u = t - b * NUPPER, ti = 0;
        while (u >= NTILE - ti) { u -= NTILE - ti; ti++; }
        const int tj = ti + u;

        const int baseI = (b * NN + ti * 32) * HIDD;
        const int baseJ = (b * NN + tj * 32) * HIDD;

        __syncthreads();
        for (int e = tid; e < 32 * HIDD; e += 256) {
            int r = e >> 6, c = e & 63;
            hI[r * PAD + c] = g_h[baseI + e];
            hJ[r * PAD + c] = g_h[baseJ + e];
        }
        for (int e = tid; e < 2 * 32 * 32; e += 256) {
            int arr = e >> 10;
            int rem = e & 1023;
            int r = rem >> 5, p = rem & 31;
            int base = arr ? baseJ : baseI;
            float2 pv = *(const float2*)&g_P[base + r * HIDD + 2 * p];
            float2 qv = *(const float2*)&g_Q[base + r * HIDD + 2 * p];
            float* dst = (arr ? PQJ : PQI) + r * SPQ + 4 * p;
            *(float4*)dst = make_float4(pv.x, pv.y, qv.x, qv.y);
        }
        __syncthreads();

        float* ob = out + (size_t)b * NN * NN;

        #pragma unroll 1
        for (int it = 0; it < 2; it++) {
            const int i0  = it * 16 + 2 * w;
            const int i1  = i0 + 1;
            const int iP0 = i0 * PAD, iP1 = i1 * PAD;
            const int iQ0 = i0 * SPQ, iQ1 = i1 * SPQ;

            uint32_t fr[2][4][8];
            #pragma unroll
            for (int kt = 0; kt < 4; kt++) {
                const int c0 = kt * 16 + 2 * tig;
                const float2 hiL0 = *(const float2*)&hI[iP0 + c0];
                const float2 hiH0 = *(const float2*)&hI[iP0 + c0 + 8];
                const float2 hiL1 = *(const float2*)&hI[iP1 + c0];
                const float2 hiH1 = *(const float2*)&hI[iP1 + c0 + 8];
                #pragma unroll
                for (int r = 0; r < 4; r++) {
                    const int rof = (gid + 8 * r) * PAD;
                    const float2 lo = *(const float2*)&hJ[rof + c0];
                    const float2 hi = *(const float2*)&hJ[rof + c0 + 8];
                    fr[0][kt][r]     = pack_bf16(fabsf(hiL0.x - lo.x), fabsf(hiL0.y - lo.y));
                    fr[0][kt][4 + r] = pack_bf16(fabsf(hiH0.x - hi.x), fabsf(hiH0.y - hi.y));
                    fr[1][kt][r]     = pack_bf16(fabsf(hiL1.x - lo.x), fabsf(hiL1.y - lo.y));
                    fr[1][kt][4 + r] = pack_bf16(fabsf(hiH1.x - hi.x), fabsf(hiH1.y - hi.y));
                }
            }

            float sij[2][4], sji[2][4];
            #pragma unroll
            for (int ii = 0; ii < 2; ii++)
                #pragma unroll
                for (int rr = 0; rr < 4; rr++) { sij[ii][rr] = 0.f; sji[ii][rr] = 0.f; }

            #pragma unroll 1
            for (int q = 0; q < 4; q++) {
                float acc[2][2][2][4];
                #pragma unroll
                for (int ii = 0; ii < 2; ii++)
                    #pragma unroll
                    for (int mt = 0; mt < 2; mt++)
                        #pragma unroll
                        for (int nx = 0; nx < 2; nx++)
                            #pragma unroll
                            for (int x = 0; x < 4; x++) acc[ii][mt][nx][x] = 0.f;

                #pragma unroll
                for (int kt = 0; kt < 4; kt++) {
                    uint4 bv = Bq[(size_t)(kt * 4 + q) * 32 + lane];
                    #pragma unroll
                    for (int ii = 0; ii < 2; ii++) {
                        mma_bf16(acc[ii][0][0], fr[ii][kt][0], fr[ii][kt][1], fr[ii][kt][4], fr[ii][kt][5], bv.x, bv.y);
                        mma_bf16(acc[ii][1][0], fr[ii][kt][2], fr[ii][kt][3], fr[ii][kt][6], fr[ii][kt][7], bv.x, bv.y);
                        mma_bf16(acc[ii][0][1], fr[ii][kt][0], fr[ii][kt][1], fr[ii][kt][4], fr[ii][kt][5], bv.z, bv.w);
                        mma_bf16(acc[ii][1][1], fr[ii][kt][2], fr[ii][kt][3], fr[ii][kt][6], fr[ii][kt][7], bv.z, bv.w);
                    }
                }

                #pragma unroll
                for (int ntl = 0; ntl < 2; ntl++) {
                    const int k0 = (2 * q + ntl) * 8 + tig * 2;
                    const float4 pqi0 = *(const float4*)&PQI[iQ0 + 2 * k0];
                    const float4 pqi1 = *(const float4*)&PQI[iQ1 + 2 * k0];
                    const float2 w2v  = *(const float2*)&w2s[k0];
                    #pragma unroll
                    for (int rr = 0; rr < 4; rr++) {
                        const int row = gid + 8 * rr;
                        const float4 pqj = *(const float4*)&PQJ[row * SPQ + 2 * k0];
                        {
                            const float dk0 = acc[0][rr >> 1][ntl][(rr & 1) * 2];
                            const float dk1 = acc[0][rr >> 1][ntl][(rr & 1) * 2 + 1];
                            sij[0][rr] = fmaf(fmaxf(dk0 + pqi0.x + pqj.z, 0.f), w2v.x, sij[0][rr]);
                            sij[0][rr] = fmaf(fmaxf(dk1 + pqi0.y + pqj.w, 0.f), w2v.y, sij[0][rr]);
                            sji[0][rr] = fmaf(fmaxf(dk0 + pqj.x + pqi0.z, 0.f), w2v.x, sji[0][rr]);
                            sji[0][rr] = fmaf(fmaxf(dk1 + pqj.y + pqi0.w, 0.f), w2v.y, sji[0][rr]);
                        }
                        {
                            const float dk0 = acc[1][rr >> 1][ntl][(rr & 1) * 2];
                            const float dk1 = acc[1][rr >> 1][ntl][(rr & 1) * 2 + 1];
                            sij[1][rr] = fmaf(fmaxf(dk0 + pqi1.x + pqj.z, 0.f), w2v.x, sij[1][rr]);
                            sij[1][rr] = fmaf(fmaxf(dk1 + pqi1.y + pqj.w, 0.f), w2v.y, sij[1][rr]);
                            sji[1][rr] = fmaf(fmaxf(dk0 + pqj.x + pqi1.z, 0.f), w2v.x, sji[1][rr]);
                            sji[1][rr] = fmaf(fmaxf(dk1 + pqj.y + pqi1.w, 0.f), w2v.y, sji[1][rr]);
                        }
                    }
                }
            }

            #pragma unroll
            for (int ii = 0; ii < 2; ii++) {
                #pragma unroll
                for (int rr = 0; rr < 4; rr++) {
                    sij[ii][rr] += __shfl_xor_sync(0xFFFFFFFF, sij[ii][rr], 1);
                    sij[ii][rr] += __shfl_xor_sync(0xFFFFFFFF, sij[ii][rr], 2);
                    sji[ii][rr] += __shfl_xor_sync(0xFFFFFFFF, sji[ii][rr], 1);
                    sji[ii][rr] += __shfl_xor_sync(0xFFFFFFFF, sji[ii][rr], 2);
                }
                const int i  = ii ? i1 : i0;
                const int j  = gid + 8 * tig;
                const int gi = ti * 32 + i, gj = tj * 32 + j;
                const float a_ij = sij[ii][tig] + b2v;
                const float a_ji = sji[ii][tig] + b2v;
                if (ti != tj || i < j) {
                    float d = 0.5f * (fast_tanh(a_ij) + fast_tanh(a_ji));
                    ob[(size_t)gi * NN + gj] = d;
                    ob[(size_t)gj * NN + gi] = d;
                } else if (i == j) {
                    ob[(size_t)gi * NN + gj] = 0.f;
                }
            }
        }
    }
}

// ---------------------------------------------------------------------------
// Kernel 3: a = relu(a_static + lam*delta); row-normalize. float4 I/O.
// ---------------------------------------------------------------------------
__global__ __launch_bounds__(192)
void finalize_kernel(const float* __restrict__ a_static,
                     const float* __restrict__ raw_lambda,
                     float* __restrict__ out)
{
    const int row = blockIdx.x;
    const int b = row / NN, i = row % NN;
    const int tid = threadIdx.x;

    const float lam = 1.f / (1.f + expf(-raw_lambda[0]));
    float4* orow = (float4*)(out + ((size_t)b * NN + i) * NN);
    const float4* arow = (const float4*)(a_static + (size_t)i * NN);

    float4 d = orow[tid];
    float4 a = arow[tid];
    float4 v;
    v.x = fmaxf(fmaf(lam, d.x, a.x), 0.f);
    v.y = fmaxf(fmaf(lam, d.y, a.y), 0.f);
    v.z = fmaxf(fmaf(lam, d.z, a.z), 0.f);
    v.w = fmaxf(fmaf(lam, d.w, a.w), 0.f);
    float s = (v.x + v.y) + (v.z + v.w);

    __shared__ float red[6];
    #pragma unroll
    for (int off = 16; off > 0; off >>= 1)
        s += __shfl_xor_sync(0xFFFFFFFF, s, off);
    if ((tid & 31) == 0) red[tid >> 5] = s;
    __syncthreads();
    float tot = red[0] + red[1] + red[2] + red[3] + red[4] + red[5];
    float inv = 1.f / fmaxf(tot, 1e-6f);
    v.x *= inv; v.y *= inv; v.z *= inv; v.w *= inv;
    orow[tid] = v;
}

// ---------------------------------------------------------------------------
extern "C" void kernel_launch(void* const* d_in, const int* in_sizes, int n_in,
                              void* d_out, int out_size)
{
    const float* x_hist   = (const float*)d_in[0];
    const float* x_mark   = (const float*)d_in[1];
    const float* a_static = (const float*)d_in[2];
    const float* te_w1 = (const float*)d_in[3];
    const float* te_b1 = (const float*)d_in[4];
    const float* te_w2 = (const float*)d_in[5];
    const float* te_b2 = (const float*)d_in[6];
    const float* me_w1 = (const float*)d_in[7];
    const float* me_b1 = (const float*)d_in[8];
    const float* me_w2 = (const float*)d_in[9];
    const float* me_b2 = (const float*)d_in[10];
    const float* nf_w  = (const float*)d_in[11];
    const float* nf_b  = (const float*)d_in[12];
    const float* ps_w1 = (const float*)d_in[13];
    const float* ps_b1 = (const float*)d_in[14];
    const float* ps_w2 = (const float*)d_in[15];
    const float* ps_b2 = (const float*)d_in[16];
    const float* raw_lambda = (const float*)d_in[17];
    float* out = (float*)d_out;

    static bool attr_set = false;
    if (!attr_set) {
        cudaFuncSetAttribute(pair_kernel,
                             cudaFuncAttributeMaxDynamicSharedMemorySize, SM_BYTES);
        cudaFuncSetAttribute(node_kernel,
                             cudaFuncAttributeMaxDynamicSharedMemorySize, NODE_SM_BYTES);
        attr_set = true;
    }

    stats_kernel<<<BB * NN, 128>>>(x_hist, x_mark, raw_lambda, out, out_size);
    node_kernel<<<GRIDN, 256, NODE_SM_BYTES>>>(
        te_w1, te_b1, te_w2, te_b2, me_w1, me_b1, me_w2, me_b2,
        nf_w, nf_b, ps_w1, ps_b1);
    pair_kernel<<<GRIDP, 256, SM_BYTES>>>(ps_w1, ps_w2, ps_b2, out);
    finalize_kernel<<<BB * NN, 192>>>(a_static, raw_lambda, out);
}

// round 17
// speedup vs baseline: 1.1337x; 1.1337x over previous
#include <cuda_runtime.h>
#include <math.h>
#include <stdint.h>

#define BB   2
#define NN   768
#define TT   96
#define FMF  8
#define HIDD 64
#define TDD  32

#define NTILE 24           // 768/32
#define NUPPER 300         // 24*25/2
#define TOTTILES (NUPPER * BB)
#define GRIDP 592          // 148 SMs * 2 CTAs
#define GRIDN 192          // 1536 / 8 nodes per block
#define PAD 68             // h tiles: word-pad for conflict-light LDS.64
#define SPQ 144            // PQ tiles: stride 144 -> LDS.128 phase-conflict-free

// ---------------------------------------------------------------------------
// helpers
// ---------------------------------------------------------------------------
__device__ __forceinline__ uint32_t pack_bf16(float lo, float hi) {
    uint32_t r;
    asm("cvt.rn.bf16x2.f32 %0, %1, %2;" : "=r"(r) : "f"(hi), "f"(lo));
    return r;
}

// tanh(x) = 1 - 2/(e^{2x}+1), via ex2.approx + rcp.approx.
__device__ __forceinline__ float fast_tanh(float x) {
    float e;
    asm("ex2.approx.f32 %0, %1;" : "=f"(e) : "f"(x * 2.8853900818f)); // 2x*log2(e)
    float r;
    asm("rcp.approx.f32 %0, %1;" : "=f"(r) : "f"(e + 1.0f));
    return fmaf(-2.0f, r, 1.0f);
}

__device__ __forceinline__ void mma_bf16(float* d,
                                         uint32_t a0, uint32_t a1, uint32_t a2, uint32_t a3,
                                         uint32_t b0, uint32_t b1) {
    asm volatile(
        "mma.sync.aligned.m16n8k16.row.col.f32.bf16.bf16.f32 "
        "{%0,%1,%2,%3}, {%4,%5,%6,%7}, {%8,%9}, {%0,%1,%2,%3};"
        : "+f"(d[0]), "+f"(d[1]), "+f"(d[2]), "+f"(d[3])
        : "r"(a0), "r"(a1), "r"(a2), "r"(a3), "r"(b0), "r"(b1));
}

// Scratch (allocation-free rule: __device__ globals)
__device__ float g_h[BB * NN * HIDD];
__device__ float g_P[BB * NN * HIDD];   // h @ w_i + ps_b1
__device__ float g_Q[BB * NN * HIDD];   // h @ w_j

// ---------------------------------------------------------------------------
// Kernel 1: per-node features. 192 blocks x 8 nodes; ONE WARP per node owns
// the whole pipeline (stats + MLP) -> intra-warp syncs only. Weights staged
// once per block (float4).
// ---------------------------------------------------------------------------
#define O_TE1 0                      // 96
#define O_TB1 (O_TE1 + 96)           // 32
#define O_ME1 (O_TB1 + 32)           // 256
#define O_MB1 (O_ME1 + 256)          // 32
#define O_TE2 (O_MB1 + 32)           // 1024
#define O_TB2 (O_TE2 + 1024)         // 32
#define O_ME2 (O_TB2 + 32)           // 1024
#define O_MB2 (O_ME2 + 1024)         // 32
#define O_NFW (O_MB2 + 32)           // 4096
#define O_NFB (O_NFW + 4096)         // 64
#define O_WI  (O_NFB + 64)           // 4096
#define O_WJ  (O_WI + 4096)          // 4096
#define O_PB1 (O_WJ + 4096)          // 64
#define O_ST  (O_PB1 + 64)           // 8*4
#define O_MS  (O_ST + 32)            // 8*8
#define O_L1  (O_MS + 64)            // 8*64
#define O_L2  (O_L1 + 512)           // 8*64
#define O_H   (O_L2 + 512)           // 8*64
#define NODE_SM_FLOATS (O_H + 512)
#define NODE_SM_BYTES (NODE_SM_FLOATS * 4)

__global__ __launch_bounds__(256)
void node_kernel(const float* __restrict__ x_hist, const float* __restrict__ x_mark,
                 const float* __restrict__ te_w1, const float* __restrict__ te_b1,
                 const float* __restrict__ te_w2, const float* __restrict__ te_b2,
                 const float* __restrict__ me_w1, const float* __restrict__ me_b1,
                 const float* __restrict__ me_w2, const float* __restrict__ me_b2,
                 const float* __restrict__ nf_w,  const float* __restrict__ nf_b,
                 const float* __restrict__ ps_w1, const float* __restrict__ ps_b1)
{
    extern __shared__ float sw[];
    const int tid  = threadIdx.x;
    const int lane = tid & 31;
    const int w    = tid >> 5;          // warp = node in block (0..7)
    const int node = blockIdx.x * 8 + w;

    // ---- stage weights (float4) ----
    {
        float4*       dNF = (float4*)(sw + O_NFW);
        float4*       dWI = (float4*)(sw + O_WI);
        float4*       dWJ = (float4*)(sw + O_WJ);
        const float4* sNF = (const float4*)nf_w;
        const float4* sWI = (const float4*)ps_w1;
        const float4* sWJ = (const float4*)(ps_w1 + HIDD * HIDD);
        #pragma unroll
        for (int e = tid; e < 1024; e += 256) {
            dNF[e] = sNF[e]; dWI[e] = sWI[e]; dWJ[e] = sWJ[e];
        }
        ((float4*)(sw + O_TE2))[tid] = ((const float4*)te_w2)[tid];
        ((float4*)(sw + O_ME2))[tid] = ((const float4*)me_w2)[tid];
        if (tid < 96) sw[O_TE1 + tid] = te_w1[tid];
        if (tid < 64) ((float4*)(sw + O_ME1))[tid] = ((const float4*)me_w1)[tid];
        if (tid < 32) {
            sw[O_TB1 + tid] = te_b1[tid]; sw[O_MB1 + tid] = me_b1[tid];
            sw[O_TB2 + tid] = te_b2[tid]; sw[O_MB2 + tid] = me_b2[tid];
        }
        if (tid < 16) {
            ((float4*)(sw + O_NFB))[tid] = ((const float4*)nf_b)[tid];
            ((float4*)(sw + O_PB1))[tid] = ((const float4*)ps_b1)[tid];
        }
    }

    // ---- stats (one node per warp; overlaps staging latency) ----
    {
        const float* xh = x_hist + (size_t)node * TT;
        const float* xm = x_mark + (size_t)node * TT * FMF;

        float v0 = xh[lane], v1 = xh[lane + 32], v2 = xh[lane + 64];
        float s  = v0 + v1 + v2;
        float mx = fmaxf(v0, fmaxf(v1, v2));
        #pragma unroll
        for (int off = 16; off > 0; off >>= 1) {
            s  += __shfl_xor_sync(0xFFFFFFFF, s, off);
            mx  = fmaxf(mx, __shfl_xor_sync(0xFFFFFFFF, mx, off));
        }
        float ms = 0.f;
        #pragma unroll
        for (int q = 0; q < 24; q++) ms += xm[lane + 32 * q];
        ms += __shfl_xor_sync(0xFFFFFFFF, ms, 8);
        ms += __shfl_xor_sync(0xFFFFFFFF, ms, 16);

        const float last = __shfl_sync(0xFFFFFFFF, v2, 31);
        if (lane == 0) {
            sw[O_ST + w * 4 + 0] = last;
            sw[O_ST + w * 4 + 1] = s * (1.f / (float)TT);
            sw[O_ST + w * 4 + 2] = mx;
        }
        if (lane < 8) sw[O_MS + w * 8 + lane] = ms * (1.f / (float)TT);
    }
    __syncthreads();   // weights + own stats visible

    const int s1  = lane;               // channel (0..31) for layer1/2
    const int ch0 = 2 * lane;           // channels for 64-wide stages

    // ---- layer 1: one t-channel + one m-channel per thread ----
    {
        float t1 = sw[O_TB1 + s1];
        #pragma unroll
        for (int c = 0; c < 3; c++)
            t1 = fmaf(sw[O_ST + w * 4 + c], sw[O_TE1 + c * TDD + s1], t1);
        float m1 = sw[O_MB1 + s1];
        #pragma unroll
        for (int c = 0; c < FMF; c++)
            m1 = fmaf(sw[O_MS + w * 8 + c], sw[O_ME1 + c * TDD + s1], m1);
        sw[O_L1 + w * 64 + s1]      = fmaxf(t1, 0.f);
        sw[O_L1 + w * 64 + 32 + s1] = fmaxf(m1, 0.f);
    }
    __syncwarp();

    // ---- layer 2 ----
    {
        float t2 = sw[O_TB2 + s1], m2 = sw[O_MB2 + s1];
        #pragma unroll
        for (int c = 0; c < TDD; c++) {
            t2 = fmaf(sw[O_L1 + w * 64 + c],      sw[O_TE2 + c * TDD + s1], t2);
            m2 = fmaf(sw[O_L1 + w * 64 + 32 + c], sw[O_ME2 + c * TDD + s1], m2);
        }
        sw[O_L2 + w * 64 + s1]      = t2;
        sw[O_L2 + w * 64 + 32 + s1] = m2;
    }
    __syncwarp();

    // ---- node fuse: 2 channels per thread ----
    {
        float2 h = *(const float2*)&sw[O_NFB + ch0];
        #pragma unroll 8
        for (int c = 0; c < HIDD; c++) {
            float a = sw[O_L2 + w * 64 + c];
            float2 wv = *(const float2*)&sw[O_NFW + c * HIDD + ch0];
            h.x = fmaf(a, wv.x, h.x); h.y = fmaf(a, wv.y, h.y);
        }
        h.x = fmaxf(h.x, 0.f); h.y = fmaxf(h.y, 0.f);
        *(float2*)&sw[O_H + w * 64 + ch0] = h;
        *(float2*)&g_h[(size_t)node * HIDD + ch0] = h;
    }
    __syncwarp();

    // ---- P / Q: 2 channels per thread ----
    {
        float2 P = *(const float2*)&sw[O_PB1 + ch0];
        float2 Q = make_float2(0.f, 0.f);
        #pragma unroll 8
        for (int c = 0; c < HIDD; c++) {
            float hv = sw[O_H + w * 64 + c];
            float2 wi = *(const float2*)&sw[O_WI + c * HIDD + ch0];
            float2 wj = *(const float2*)&sw[O_WJ + c * HIDD + ch0];
            P.x = fmaf(hv, wi.x, P.x); P.y = fmaf(hv, wi.y, P.y);
            Q.x = fmaf(hv, wj.x, Q.x); Q.y = fmaf(hv, wj.y, Q.y);
        }
        *(float2*)&g_P[(size_t)node * HIDD + ch0] = P;
        *(float2*)&g_Q[(size_t)node * HIDD + ch0] = Q;
    }
}

// ---------------------------------------------------------------------------
// Kernel 2: pairwise delta via bf16 m16n8k16. Two i-rows per warp, persistent
// A-fragments, quarter-N acc, float4-interleaved P/Q. (R15-identical.)
// ---------------------------------------------------------------------------
#define BF_BYTES (4 * 4 * 32 * 16)                   // uint4 table, 8 KB
#define SM_FLOATS_P (2 * 32 * PAD + 2 * 32 * SPQ + 64)
#define SM_BYTES (BF_BYTES + SM_FLOATS_P * 4)

__global__ __launch_bounds__(256, 2)
void pair_kernel(const float* __restrict__ ps_w1, const float* __restrict__ ps_w2,
                 const float* __restrict__ ps_b2, float* __restrict__ out)
{
    extern __shared__ __align__(16) char smx[];
    uint4* Bq = (uint4*)smx;                         // [kt][q][lane]
    float* fp = (float*)(smx + BF_BYTES);
    float* hI  = fp;                                 // [32][PAD]
    float* hJ  = hI + 32 * PAD;
    float* PQI = hJ + 32 * PAD;                      // [32][SPQ]
    float* PQJ = PQI + 32 * SPQ;
    float* w2s = PQJ + 32 * SPQ;                     // [64]

    const int tid  = threadIdx.x;
    const int w    = tid >> 5;
    const int lane = tid & 31;
    const int gid  = lane >> 2;                      // 0..7
    const int tig  = lane & 3;                       // 0..3

    // B fragment table (uint4 of bf16x2), tile-independent: load once.
    {
        const float* wd = ps_w1 + 128 * HIDD;
        for (int e = tid; e < 4 * 4 * 32; e += 256) {
            int ktp = e >> 5, ln = e & 31;
            int kt = ktp >> 2, q = ktp & 3;
            int gd = ln >> 2, tg = ln & 3;
            int k0 = kt * 16 + 2 * tg;
            int n0 = 2 * q * 8 + gd, n1 = n0 + 8;
            uint4 v;
            v.x = pack_bf16(wd[k0 * HIDD + n0],       wd[(k0 + 1) * HIDD + n0]);
            v.y = pack_bf16(wd[(k0 + 8) * HIDD + n0], wd[(k0 + 9) * HIDD + n0]);
            v.z = pack_bf16(wd[k0 * HIDD + n1],       wd[(k0 + 1) * HIDD + n1]);
            v.w = pack_bf16(wd[(k0 + 8) * HIDD + n1], wd[(k0 + 9) * HIDD + n1]);
            Bq[(size_t)ktp * 32 + ln] = v;
        }
    }
    if (tid < 64) w2s[tid] = ps_w2[tid];
    const float b2v = ps_b2[0];

    #pragma unroll 1
    for (int t = blockIdx.x; t < TOTTILES; t += GRIDP) {
        const int b = t / NUPPER;
        int u = t - b * NUPPER, ti = 0;
        while (u >= NTILE - ti) { u -= NTILE - ti; ti++; }
        const int tj = ti + u;

        const int baseI = (b * NN + ti * 32) * HIDD;
        const int baseJ = (b * NN + tj * 32) * HIDD;

        __syncthreads();
        for (int e = tid; e < 32 * HIDD; e += 256) {
            int r = e >> 6, c = e & 63;
            hI[r * PAD + c] = g_h[baseI + e];
            hJ[r * PAD + c] = g_h[baseJ + e];
        }
        for (int e = tid; e < 2 * 32 * 32; e += 256) {
            int arr = e >> 10;
            int rem = e & 1023;
            int r = rem >> 5, p = rem & 31;
            int base = arr ? baseJ : baseI;
            float2 pv = *(const float2*)&g_P[base + r * HIDD + 2 * p];
            float2 qv = *(const float2*)&g_Q[base + r * HIDD + 2 * p];
            float* dst = (arr ? PQJ : PQI) + r * SPQ + 4 * p;
            *(float4*)dst = make_float4(pv.x, pv.y, qv.x, qv.y);
        }
        __syncthreads();

        float* ob = out + (size_t)b * NN * NN;

        #pragma unroll 1
        for (int it = 0; it < 2; it++) {
            const int i0  = it * 16 + 2 * w;
            const int i1  = i0 + 1;
            const int iP0 = i0 * PAD, iP1 = i1 * PAD;
            const int iQ0 = i0 * SPQ, iQ1 = i1 * SPQ;

            uint32_t fr[2][4][8];
            #pragma unroll
            for (int kt = 0; kt < 4; kt++) {
                const int c0 = kt * 16 + 2 * tig;
                const float2 hiL0 = *(const float2*)&hI[iP0 + c0];
                const float2 hiH0 = *(const float2*)&hI[iP0 + c0 + 8];
                const float2 hiL1 = *(const float2*)&hI[iP1 + c0];
                const float2 hiH1 = *(const float2*)&hI[iP1 + c0 + 8];
                #pragma unroll
                for (int r = 0; r < 4; r++) {
                    const int rof = (gid + 8 * r) * PAD;
                    const float2 lo = *(const float2*)&hJ[rof + c0];
                    const float2 hi = *(const float2*)&hJ[rof + c0 + 8];
                    fr[0][kt][r]     = pack_bf16(fabsf(hiL0.x - lo.x), fabsf(hiL0.y - lo.y));
                    fr[0][kt][4 + r] = pack_bf16(fabsf(hiH0.x - hi.x), fabsf(hiH0.y - hi.y));
                    fr[1][kt][r]     = pack_bf16(fabsf(hiL1.x - lo.x), fabsf(hiL1.y - lo.y));
                    fr[1][kt][4 + r] = pack_bf16(fabsf(hiH1.x - hi.x), fabsf(hiH1.y - hi.y));
                }
            }

            float sij[2][4], sji[2][4];
            #pragma unroll
            for (int ii = 0; ii < 2; ii++)
                #pragma unroll
                for (int rr = 0; rr < 4; rr++) { sij[ii][rr] = 0.f; sji[ii][rr] = 0.f; }

            #pragma unroll 1
            for (int q = 0; q < 4; q++) {
                float acc[2][2][2][4];
                #pragma unroll
                for (int ii = 0; ii < 2; ii++)
                    #pragma unroll
                    for (int mt = 0; mt < 2; mt++)
                        #pragma unroll
                        for (int nx = 0; nx < 2; nx++)
                            #pragma unroll
                            for (int x = 0; x < 4; x++) acc[ii][mt][nx][x] = 0.f;

                #pragma unroll
                for (int kt = 0; kt < 4; kt++) {
                    uint4 bv = Bq[(size_t)(kt * 4 + q) * 32 + lane];
                    #pragma unroll
                    for (int ii = 0; ii < 2; ii++) {
                        mma_bf16(acc[ii][0][0], fr[ii][kt][0], fr[ii][kt][1], fr[ii][kt][4], fr[ii][kt][5], bv.x, bv.y);
                        mma_bf16(acc[ii][1][0], fr[ii][kt][2], fr[ii][kt][3], fr[ii][kt][6], fr[ii][kt][7], bv.x, bv.y);
                        mma_bf16(acc[ii][0][1], fr[ii][kt][0], fr[ii][kt][1], fr[ii][kt][4], fr[ii][kt][5], bv.z, bv.w);
                        mma_bf16(acc[ii][1][1], fr[ii][kt][2], fr[ii][kt][3], fr[ii][kt][6], fr[ii][kt][7], bv.z, bv.w);
                    }
                }

                #pragma unroll
                for (int ntl = 0; ntl < 2; ntl++) {
                    const int k0 = (2 * q + ntl) * 8 + tig * 2;
                    const float4 pqi0 = *(const float4*)&PQI[iQ0 + 2 * k0];
                    const float4 pqi1 = *(const float4*)&PQI[iQ1 + 2 * k0];
                    const float2 w2v  = *(const float2*)&w2s[k0];
                    #pragma unroll
                    for (int rr = 0; rr < 4; rr++) {
                        const int row = gid + 8 * rr;
                        const float4 pqj = *(const float4*)&PQJ[row * SPQ + 2 * k0];
                        {
                            const float dk0 = acc[0][rr >> 1][ntl][(rr & 1) * 2];
                            const float dk1 = acc[0][rr >> 1][ntl][(rr & 1) * 2 + 1];
                            sij[0][rr] = fmaf(fmaxf(dk0 + pqi0.x + pqj.z, 0.f), w2v.x, sij[0][rr]);
                            sij[0][rr] = fmaf(fmaxf(dk1 + pqi0.y + pqj.w, 0.f), w2v.y, sij[0][rr]);
                            sji[0][rr] = fmaf(fmaxf(dk0 + pqj.x + pqi0.z, 0.f), w2v.x, sji[0][rr]);
                            sji[0][rr] = fmaf(fmaxf(dk1 + pqj.y + pqi0.w, 0.f), w2v.y, sji[0][rr]);
                        }
                        {
                            const float dk0 = acc[1][rr >> 1][ntl][(rr & 1) * 2];
                            const float dk1 = acc[1][rr >> 1][ntl][(rr & 1) * 2 + 1];
                            sij[1][rr] = fmaf(fmaxf(dk0 + pqi1.x + pqj.z, 0.f), w2v.x, sij[1][rr]);
                            sij[1][rr] = fmaf(fmaxf(dk1 + pqi1.y + pqj.w, 0.f), w2v.y, sij[1][rr]);
                            sji[1][rr] = fmaf(fmaxf(dk0 + pqj.x + pqi1.z, 0.f), w2v.x, sji[1][rr]);
                            sji[1][rr] = fmaf(fmaxf(dk1 + pqj.y + pqi1.w, 0.f), w2v.y, sji[1][rr]);
                        }
                    }
                }
            }

            #pragma unroll
            for (int ii = 0; ii < 2; ii++) {
                #pragma unroll
                for (int rr = 0; rr < 4; rr++) {
                    sij[ii][rr] += __shfl_xor_sync(0xFFFFFFFF, sij[ii][rr], 1);
                    sij[ii][rr] += __shfl_xor_sync(0xFFFFFFFF, sij[ii][rr], 2);
                    sji[ii][rr] += __shfl_xor_sync(0xFFFFFFFF, sji[ii][rr], 1);
                    sji[ii][rr] += __shfl_xor_sync(0xFFFFFFFF, sji[ii][rr], 2);
                }
                const int i  = ii ? i1 : i0;
                const int j  = gid + 8 * tig;
                const int gi = ti * 32 + i, gj = tj * 32 + j;
                const float a_ij = sij[ii][tig] + b2v;
                const float a_ji = sji[ii][tig] + b2v;
                if (ti != tj || i < j) {
                    float d = 0.5f * (fast_tanh(a_ij) + fast_tanh(a_ji));
                    ob[(size_t)gi * NN + gj] = d;
                    ob[(size_t)gj * NN + gi] = d;
                } else if (i == j) {
                    ob[(size_t)gi * NN + gj] = 0.f;
                }
            }
        }
    }
}

// ---------------------------------------------------------------------------
// Kernel 3: a = relu(a_static + lam*delta); row-normalize; lam tail-write.
// ---------------------------------------------------------------------------
__global__ __launch_bounds__(192)
void finalize_kernel(const float* __restrict__ a_static,
                     const float* __restrict__ raw_lambda,
                     float* __restrict__ out, int out_size)
{
    const int row = blockIdx.x;
    const int b = row / NN, i = row % NN;
    const int tid = threadIdx.x;

    const float lam = 1.f / (1.f + expf(-raw_lambda[0]));
    float4* orow = (float4*)(out + ((size_t)b * NN + i) * NN);
    const float4* arow = (const float4*)(a_static + (size_t)i * NN);

    float4 d = orow[tid];
    float4 a = arow[tid];
    float4 v;
    v.x = fmaxf(fmaf(lam, d.x, a.x), 0.f);
    v.y = fmaxf(fmaf(lam, d.y, a.y), 0.f);
    v.z = fmaxf(fmaf(lam, d.z, a.z), 0.f);
    v.w = fmaxf(fmaf(lam, d.w, a.w), 0.f);
    float s = (v.x + v.y) + (v.z + v.w);

    __shared__ float red[6];
    #pragma unroll
    for (int off = 16; off > 0; off >>= 1)
        s += __shfl_xor_sync(0xFFFFFFFF, s, off);
    if ((tid & 31) == 0) red[tid >> 5] = s;
    __syncthreads();
    float tot = red[0] + red[1] + red[2] + red[3] + red[4] + red[5];
    float inv = 1.f / fmaxf(tot, 1e-6f);
    v.x *= inv; v.y *= inv; v.z *= inv; v.w *= inv;
    orow[tid] = v;

    if (row == 0 && tid == 0) {
        for (int idx = BB * NN * NN; idx < out_size; idx++) out[idx] = lam;
    }
}

// ---------------------------------------------------------------------------
extern "C" void kernel_launch(void* const* d_in, const int* in_sizes, int n_in,
                              void* d_out, int out_size)
{
    const float* x_hist   = (const float*)d_in[0];
    const float* x_mark   = (const float*)d_in[1];
    const float* a_static = (const float*)d_in[2];
    const float* te_w1 = (const float*)d_in[3];
    const float* te_b1 = (const float*)d_in[4];
    const float* te_w2 = (const float*)d_in[5];
    const float* te_b2 = (const float*)d_in[6];
    const float* me_w1 = (const float*)d_in[7];
    const float* me_b1 = (const float*)d_in[8];
    const float* me_w2 = (const float*)d_in[9];
    const float* me_b2 = (const float*)d_in[10];
    const float* nf_w  = (const float*)d_in[11];
    const float* nf_b  = (const float*)d_in[12];
    const float* ps_w1 = (const float*)d_in[13];
    const float* ps_b1 = (const float*)d_in[14];
    const float* ps_w2 = (const float*)d_in[15];
    const float* ps_b2 = (const float*)d_in[16];
    const float* raw_lambda = (const float*)d_in[17];
    float* out = (float*)d_out;

    static bool attr_set = false;
    if (!attr_set) {
        cudaFuncSetAttribute(pair_kernel,
                             cudaFuncAttributeMaxDynamicSharedMemorySize, SM_BYTES);
        cudaFuncSetAttribute(node_kernel,
                             cudaFuncAttributeMaxDynamicSharedMemorySize, NODE_SM_BYTES);
        attr_set = true;
    }

    node_kernel<<<GRIDN, 256, NODE_SM_BYTES>>>(
        x_hist, x_mark, te_w1, te_b1, te_w2, te_b2,
        me_w1, me_b1, me_w2, me_b2, nf_w, nf_b, ps_w1, ps_b1);
    pair_kernel<<<GRIDP, 256, SM_BYTES>>>(ps_w1, ps_w2, ps_b2, out);
    finalize_kernel<<<BB * NN, 192>>>(a_static, raw_lambda, out, out_size);
}